// round 1
// baseline (speedup 1.0000x reference)
#include <cuda_runtime.h>

#define EPS 1e-6f
#define BLOCK 256
#define MAX_PARTIALS 8192

// Scratch for deterministic two-pass reduction (no cudaMalloc allowed).
__device__ float2 g_partials[MAX_PARTIALS];

__device__ __forceinline__ float norm2f(float x, float y) {
    return sqrtf(x * x + y * y);
}

__global__ void __launch_bounds__(BLOCK)
gsc_main_kernel(const float* __restrict__ pred,
                const float* __restrict__ gt,
                int nrows)
{
    const int row = blockIdx.x * BLOCK + threadIdx.x;

    float L = 0.0f;
    float cnt = 0.0f;

    if (row < nrows) {
        // Each row: 8 kpts * 3 floats = 24 floats = 6 float4 (96B, 16B aligned).
        const float4* p4 = reinterpret_cast<const float4*>(pred + (size_t)row * 24);
        const float4* q4 = reinterpret_cast<const float4*>(gt   + (size_t)row * 24);

        float pv[24], gv[24];
        #pragma unroll
        for (int i = 0; i < 6; i++) {
            float4 a = p4[i];
            pv[4*i+0] = a.x; pv[4*i+1] = a.y; pv[4*i+2] = a.z; pv[4*i+3] = a.w;
        }
        #pragma unroll
        for (int i = 0; i < 6; i++) {
            float4 b = q4[i];
            gv[4*i+0] = b.x; gv[4*i+1] = b.y; gv[4*i+2] = b.z; gv[4*i+3] = b.w;
        }

        // First 4 visible keypoints (stable order), count all visible.
        // Unrolled predicated selects -> stays in registers.
        float px[4], py[4], gx[4], gy[4];
        int nv = 0;
        #pragma unroll
        for (int k = 0; k < 8; k++) {
            const bool vis = (pv[3*k+2] > 0.5f) && (gv[3*k+2] > 0.5f);
            if (vis) {
                if (nv == 0)      { px[0]=pv[3*k]; py[0]=pv[3*k+1]; gx[0]=gv[3*k]; gy[0]=gv[3*k+1]; }
                else if (nv == 1) { px[1]=pv[3*k]; py[1]=pv[3*k+1]; gx[1]=gv[3*k]; gy[1]=gv[3*k+1]; }
                else if (nv == 2) { px[2]=pv[3*k]; py[2]=pv[3*k+1]; gx[2]=gv[3*k]; gy[2]=gv[3*k+1]; }
                else if (nv == 3) { px[3]=pv[3*k]; py[3]=pv[3*k+1]; gx[3]=gv[3*k]; gy[3]=gv[3*k+1]; }
                nv++;
            }
        }

        if (nv >= 4) {
            // ---- L_shape: cross ratio ----
            const float pred_cr = norm2f(px[2]-px[0], py[2]-py[0]) /
                                  (norm2f(px[3]-px[1], py[3]-py[1]) + EPS);
            const float gt_cr   = norm2f(gx[2]-gx[0], gy[2]-gy[0]) /
                                  (norm2f(gx[3]-gx[1], gy[3]-gy[1]) + EPS);
            const float L_shape = fabsf(pred_cr - gt_cr);

            // ---- L_edge ----
            const float v12x = px[1]-px[0], v12y = py[1]-py[0];
            const float v23x = px[2]-px[1], v23y = py[2]-py[1];
            const float v34x = px[3]-px[2], v34y = py[3]-py[2];
            const float v41x = px[0]-px[3], v41y = py[0]-py[3];
            const float l12 = norm2f(v12x, v12y);
            const float l23 = norm2f(v23x, v23y);
            const float l34 = norm2f(v34x, v34y);
            const float l41 = norm2f(v41x, v41y);

            const float par1 = fabsf(l12 - l34) / (l12 + l34 + EPS);
            const float par2 = fabsf(l23 - l41) / (l23 + l41 + EPS);
            const float dot1 = fabsf((v12x*v41x + v12y*v41y) / (l12*l41 + EPS));
            const float dot2 = fabsf((v12x*v23x + v12y*v23y) / (l12*l23 + EPS));
            const float dot3 = fabsf((v23x*v34x + v23y*v34y) / (l23*l34 + EPS));
            const float dot4 = fabsf((v34x*v41x + v34y*v41y) / (l34*l41 + EPS));
            const float L_edge = (par1 + par2) * 0.5f + (dot1 + dot2 + dot3 + dot4) * 0.25f;

            // ---- L_pos ----
            float dist = 0.0f;
            #pragma unroll
            for (int i = 0; i < 4; i++)
                dist += norm2f(px[i]-gx[i], py[i]-gy[i]);
            dist *= 0.25f;

            // quad areas: 0.5*|cross(p1-p0, p2-p0)| + 0.5*|cross(p2-p0, p3-p0)|
            const float pax1 = px[1]-px[0], pay1 = py[1]-py[0];
            const float pax2 = px[2]-px[0], pay2 = py[2]-py[0];
            const float pax3 = px[3]-px[0], pay3 = py[3]-py[0];
            const float pred_area = 0.5f * fabsf(pax1*pay2 - pay1*pax2)
                                  + 0.5f * fabsf(pax2*pay3 - pay2*pax3);
            const float gax1 = gx[1]-gx[0], gay1 = gy[1]-gy[0];
            const float gax2 = gx[2]-gx[0], gay2 = gy[2]-gy[0];
            const float gax3 = gx[3]-gx[0], gay3 = gy[3]-gy[0];
            const float gt_area = 0.5f * fabsf(gax1*gay2 - gay1*gax2)
                                + 0.5f * fabsf(gax2*gay3 - gay2*gax3);
            const float area_ratio = fabsf(pred_area - gt_area) / (gt_area + EPS);

            const float pmx = 0.25f * (px[0]+px[1]+px[2]+px[3]);
            const float pmy = 0.25f * (py[0]+py[1]+py[2]+py[3]);
            const float gmx = 0.25f * (gx[0]+gx[1]+gx[2]+gx[3]);
            const float gmy = 0.25f * (gy[0]+gy[1]+gy[2]+gy[3]);
            float rel_cons = 0.0f;
            #pragma unroll
            for (int i = 0; i < 4; i++)
                rel_cons += norm2f((px[i]-pmx) - (gx[i]-gmx),
                                   (py[i]-pmy) - (gy[i]-gmy));
            rel_cons *= 0.25f;

            const float L_pos = 0.4f * dist + 0.3f * area_ratio + 0.3f * rel_cons;

            L = 0.4f * L_shape + 0.3f * L_edge + 0.3f * L_pos;
            cnt = 1.0f;
        }
    }

    // ---- block reduction (deterministic) ----
    #pragma unroll
    for (int off = 16; off > 0; off >>= 1) {
        L   += __shfl_down_sync(0xffffffffu, L,   off);
        cnt += __shfl_down_sync(0xffffffffu, cnt, off);
    }
    __shared__ float sL[BLOCK / 32];
    __shared__ float sC[BLOCK / 32];
    const int warp = threadIdx.x >> 5;
    const int lane = threadIdx.x & 31;
    if (lane == 0) { sL[warp] = L; sC[warp] = cnt; }
    __syncthreads();
    if (warp == 0) {
        L   = (lane < BLOCK / 32) ? sL[lane] : 0.0f;
        cnt = (lane < BLOCK / 32) ? sC[lane] : 0.0f;
        #pragma unroll
        for (int off = 4; off > 0; off >>= 1) {
            L   += __shfl_down_sync(0xffffffffu, L,   off);
            cnt += __shfl_down_sync(0xffffffffu, cnt, off);
        }
        if (lane == 0) g_partials[blockIdx.x] = make_float2(L, cnt);
    }
}

__global__ void __launch_bounds__(BLOCK)
gsc_final_kernel(float* __restrict__ out, int nblocks)
{
    float L = 0.0f, C = 0.0f;
    for (int i = threadIdx.x; i < nblocks; i += BLOCK) {
        float2 v = g_partials[i];
        L += v.x;
        C += v.y;
    }
    #pragma unroll
    for (int off = 16; off > 0; off >>= 1) {
        L += __shfl_down_sync(0xffffffffu, L, off);
        C += __shfl_down_sync(0xffffffffu, C, off);
    }
    __shared__ float sL[BLOCK / 32];
    __shared__ float sC[BLOCK / 32];
    const int warp = threadIdx.x >> 5;
    const int lane = threadIdx.x & 31;
    if (lane == 0) { sL[warp] = L; sC[warp] = C; }
    __syncthreads();
    if (warp == 0) {
        L = (lane < BLOCK / 32) ? sL[lane] : 0.0f;
        C = (lane < BLOCK / 32) ? sC[lane] : 0.0f;
        #pragma unroll
        for (int off = 4; off > 0; off >>= 1) {
            L += __shfl_down_sync(0xffffffffu, L, off);
            C += __shfl_down_sync(0xffffffffu, C, off);
        }
        if (lane == 0) {
            out[0] = (C > 0.5f) ? (L / C) : 0.0f;
        }
    }
}

extern "C" void kernel_launch(void* const* d_in, const int* in_sizes, int n_in,
                              void* d_out, int out_size)
{
    const float* pred = (const float*)d_in[0];
    const float* gt   = (const float*)d_in[1];
    float* out = (float*)d_out;

    const int nrows = in_sizes[0] / 24;   // B*K*3 floats, K=8 -> 24 floats per row
    int nblocks = (nrows + BLOCK - 1) / BLOCK;
    if (nblocks > MAX_PARTIALS) nblocks = MAX_PARTIALS;  // (524288/256 = 2048, safe)

    gsc_main_kernel<<<nblocks, BLOCK>>>(pred, gt, nrows);
    gsc_final_kernel<<<1, BLOCK>>>(out, nblocks);
}